// round 9
// baseline (speedup 1.0000x reference)
#include <cuda_runtime.h>
#include <cuda_fp16.h>
#include <cstdint>

#define BB   512
#define TT   100
#define LL   256
#define DD   128
#define PP   9
#define NSEQ (BB*TT)
#define NG   512
#define MROWS 128
#define NBLK (NSEQ/MROWS)   // 400
#define NTHR 512
#define ROWB  272            // padded row stride bytes
#define CHUNK (128*ROWB)     // 34816
#define WBYTES (4*CHUNK)     // 139264

// ---- LSTM kernel SMEM ----
#define SM_WHH  0            // 139264 resident Whh (4 chunks)
#define SM_AH0  139264       // 34816  h tile buf0
#define SM_AH1  174080       // 34816  h tile buf1
#define SM_ACT  208896       // 512
#define SM_MBAR 209472       // 8
#define SMEM_SZ 209536

// ---- gx kernel SMEM ----
#define SX_W    0            // 139264 Wih
#define SX_AX   139264       // 34816  x tile
#define SX_BIAS 174080       // 2048
#define SX_NID  176128       // 512
#define SX_MBAR 176704       // 8
#define SMEM_GX 176768

__device__ __align__(128) unsigned char g_Wih[WBYTES];
__device__ __align__(128) unsigned char g_Whh[WBYTES];
__device__ float g_bias[NG];
__device__ int   g_nids[NSEQ*PP];
__device__ int   g_active[NSEQ];
// gx in raw MMA-fragment layout, fp16: [p][blk][tid][16 x uint4]
__device__ uint4 g_gx[(size_t)PP*NBLK*NTHR*16];

__device__ __forceinline__ float sigf(float x)   { return 1.0f / (1.0f + __expf(-x)); }
__device__ __forceinline__ float tanhf_(float x) { return 1.0f - 2.0f / (__expf(2.0f*x) + 1.0f); }

__device__ __forceinline__ uint32_t smem_u32(const void* p) {
    uint32_t a;
    asm("{ .reg .u64 t; cvta.to.shared.u64 t, %1; cvt.u32.u64 %0, t; }" : "=r"(a) : "l"(p));
    return a;
}
__device__ __forceinline__ void mbar_init(uint32_t mbar, uint32_t cnt) {
    asm volatile("mbarrier.init.shared.b64 [%0], %1;" :: "r"(mbar), "r"(cnt) : "memory");
}
__device__ __forceinline__ void mbar_expect_tx(uint32_t mbar, uint32_t bytes) {
    asm volatile("mbarrier.arrive.expect_tx.shared.b64 _, [%0], %1;" :: "r"(mbar), "r"(bytes) : "memory");
}
__device__ __forceinline__ void mbar_wait(uint32_t mbar, uint32_t ph) {
    asm volatile(
        "{\n\t.reg .pred P;\n\tLW_%=:\n\t"
        "mbarrier.try_wait.parity.acquire.cta.shared::cta.b64 P, [%0], %1, 0x989680;\n\t"
        "@P bra LD_%=;\n\tbra LW_%=;\n\tLD_%=:\n\t}"
        :: "r"(mbar), "r"(ph) : "memory");
}
__device__ __forceinline__ void bulk_g2s(uint32_t dst, const void* src, uint32_t bytes, uint32_t mbar) {
    asm volatile(
        "cp.async.bulk.shared::cluster.global.mbarrier::complete_tx::bytes [%0], [%1], %2, [%3];"
        :: "r"(dst), "l"(src), "r"(bytes), "r"(mbar) : "memory");
}
__device__ __forceinline__ void fence_async() {
    asm volatile("fence.proxy.async.shared::cta;" ::: "memory");
}
__device__ __forceinline__ void mma16816h(float* d, const uint32_t* a, const uint32_t* b) {
    asm volatile(
        "mma.sync.aligned.m16n8k16.row.col.f32.f16.f16.f32 "
        "{%0,%1,%2,%3}, {%4,%5,%6,%7}, {%8,%9}, {%0,%1,%2,%3};"
        : "+f"(d[0]), "+f"(d[1]), "+f"(d[2]), "+f"(d[3])
        : "r"(a[0]), "r"(a[1]), "r"(a[2]), "r"(a[3]), "r"(b[0]), "r"(b[1]));
}
__device__ __forceinline__ void ldsm4(uint32_t* r, uint32_t addr) {
    asm volatile("ldmatrix.sync.aligned.m8n8.x4.shared.b16 {%0,%1,%2,%3}, [%4];"
        : "=r"(r[0]), "=r"(r[1]), "=r"(r[2]), "=r"(r[3]) : "r"(addr));
}

// One [64m x 16n x 128k] warp product-accumulate (fp16 operands).
__device__ __forceinline__ void gemm_pass(uint32_t abase, const char* __restrict__ W,
                                          int nw, int g, int tg, float d[4][2][4]) {
#pragma unroll
    for (int k8 = 0; k8 < 8; k8++) {
        uint32_t a[4][4], b[2][2];
#pragma unroll
        for (int mi = 0; mi < 4; mi++)
            ldsm4(a[mi], abase + mi*(16*ROWB) + k8*32);
        const int kb = (k8*16 + tg*2) * 2;
#pragma unroll
        for (int ni = 0; ni < 2; ni++) {
            const char* wr = W + (nw*16 + ni*8 + g)*ROWB + kb;
            b[ni][0] = *(const uint32_t*)wr;
            b[ni][1] = *(const uint32_t*)(wr + 16);
        }
#pragma unroll
        for (int mi = 0; mi < 4; mi++)
#pragma unroll
            for (int ni = 0; ni < 2; ni++)
                mma16816h(d[mi][ni], a[mi], b[ni]);
    }
}

// ---------------------------------------------------------------------------
// prep: fp16 W images (row n=(j&31)*4+gate, 272B rows, chunk q=j>>5) + bias
// ---------------------------------------------------------------------------
__global__ void prep_kernel(const float* __restrict__ w_ih, const float* __restrict__ w_hh,
                            const float* __restrict__ b_ih, const float* __restrict__ b_hh) {
    int idx = blockIdx.x * blockDim.x + threadIdx.x;
    if (idx < NG) g_bias[idx] = b_ih[idx] + b_hh[idx];
    if (idx >= 2 * NG * DD) return;
    int part = idx >> 16;
    int rem  = idx & 65535;
    int r = rem >> 7;
    int k = rem & 127;
    int gate = r >> 7, j = r & 127;
    int q = j >> 5;
    int n = ((j & 31) << 2) | gate;
    float w = (part == 0) ? w_ih[r * DD + k] : w_hh[r * DD + k];
    unsigned char* base = (part == 0) ? g_Wih : g_Whh;
    *(__half*)(base + q*CHUNK + n*ROWB + k*2) = __float2half(w);
}

// ---------------------------------------------------------------------------
__global__ void leaf_kernel(const float* __restrict__ cross, const int* __restrict__ paths) {
    int warp = (blockIdx.x * blockDim.x + threadIdx.x) >> 5;
    int lane = threadIdx.x & 31;
    if (warp >= NSEQ) return;
    int b = warp / TT;
    int t = warp - b * TT;
    const float* row = cross + (size_t)b * (TT*LL) + (size_t)t * LL;
    float bv = -3.0e38f; int bl = 0; int anyp = 0;
#pragma unroll
    for (int i = 0; i < LL/32; i++) {
        int l = lane + 32*i;
        float v = row[l];
        if (v > 0.0f) anyp = 1;
        if (v > bv) { bv = v; bl = l; }
    }
#pragma unroll
    for (int off = 16; off > 0; off >>= 1) {
        float ov = __shfl_down_sync(0xffffffffu, bv, off);
        int   ol = __shfl_down_sync(0xffffffffu, bl, off);
        if (ov > bv || (ov == bv && ol < bl)) { bv = ov; bl = ol; }
    }
    anyp = __any_sync(0xffffffffu, anyp);
    int leaf = __shfl_sync(0xffffffffu, bl, 0);
    if (lane < PP) g_nids[warp*PP + lane] = paths[((size_t)t*LL + leaf)*PP + lane];
    if (lane == 0) g_active[warp] = anyp;
}

// ---------------------------------------------------------------------------
// gx kernel: per (blk, p): gx = x @ Wih^T + bias, stored fp16 raw-fragment
// ---------------------------------------------------------------------------
__global__ void __launch_bounds__(NTHR, 1)
gx_kernel(const float* __restrict__ node_emb) {
    extern __shared__ __align__(16) char smem[];
    const uint32_t sb = smem_u32(smem);
    const int tid  = threadIdx.x;
    const int wid  = tid >> 5, lane = tid & 31;
    const int g    = lane >> 2, tg = lane & 3;
    const int mw   = wid >> 3, nw = wid & 7;
    const int blk  = blockIdx.x, p = blockIdx.y;
    const int bt0  = blk * MROWS;

    if (tid == 0) {
        mbar_init(sb + SX_MBAR, 1);
        fence_async();
        mbar_expect_tx(sb + SX_MBAR, WBYTES);
        bulk_g2s(sb + SX_W, g_Wih, WBYTES, sb + SX_MBAR);
    }
    int* snid = (int*)(smem + SX_NID);
    float* sbias = (float*)(smem + SX_BIAS);
    if (tid < MROWS) snid[tid] = g_nids[(bt0 + tid)*PP + p];
    if (tid < NG)    sbias[tid] = g_bias[tid];
    __syncthreads();

    // gather x into A_x (fp16, ROWB-padded)
#pragma unroll
    for (int i = 0; i < 8; i++) {
        int idx = i * NTHR + tid;
        int mm = idx >> 5, kq = (idx & 31) << 2;
        const float4 v = *(const float4*)(node_emb + (size_t)snid[mm]*DD + kq);
        __half2 a = __floats2half2_rn(v.x, v.y);
        __half2 b = __floats2half2_rn(v.z, v.w);
        uint2 pk; pk.x = *(uint32_t*)&a; pk.y = *(uint32_t*)&b;
        *(uint2*)(smem + SX_AX + mm*ROWB + kq*2) = pk;
    }
    mbar_wait(sb + SX_MBAR, 0);
    __syncthreads();

    const uint32_t lrow = lane & 15;
    const uint32_t lcol = (lane & 16) ? 16u : 0u;
    const uint32_t ax_b = sb + SX_AX + (mw*64 + lrow)*ROWB + lcol;

    uint4* gxout = g_gx + ((size_t)(p*NBLK + blk)*NTHR + tid)*16;

#pragma unroll
    for (int q = 0; q < 4; q++) {
        float d[4][2][4];
#pragma unroll
        for (int mi = 0; mi < 4; mi++)
#pragma unroll
            for (int ni = 0; ni < 2; ni++)
#pragma unroll
                for (int e = 0; e < 4; e++) d[mi][ni][e] = 0.0f;
        gemm_pass(ax_b, smem + SX_W + q*CHUNK, nw, g, tg, d);

        uint32_t outw[16];
#pragma unroll
        for (int ni = 0; ni < 2; ni++) {
            const int n_even = nw*16 + ni*8 + 2*tg;
            const int n_odd  = n_even + 1;
            const float b_e = sbias[(n_even & 3)*128 + q*32 + (n_even >> 2)];
            const float b_o = sbias[(n_odd  & 3)*128 + q*32 + (n_odd  >> 2)];
#pragma unroll
            for (int mi = 0; mi < 4; mi++) {
                __half2 h01 = __floats2half2_rn(d[mi][ni][0] + b_e, d[mi][ni][1] + b_o);
                __half2 h23 = __floats2half2_rn(d[mi][ni][2] + b_e, d[mi][ni][3] + b_o);
                outw[(ni*4 + mi)*2 + 0] = *(uint32_t*)&h01;
                outw[(ni*4 + mi)*2 + 1] = *(uint32_t*)&h23;
            }
        }
#pragma unroll
        for (int i = 0; i < 4; i++)
            gxout[q*4 + i] = make_uint4(outw[4*i], outw[4*i+1], outw[4*i+2], outw[4*i+3]);
    }
}

// ---------------------------------------------------------------------------
// LSTM kernel: Whh resident, gx from global, double-buffered h tiles
// ---------------------------------------------------------------------------
__global__ void __launch_bounds__(NTHR, 1)
lstm_mma(float* __restrict__ out) {
    extern __shared__ __align__(16) char smem[];
    const uint32_t sb = smem_u32(smem);
    const int tid  = threadIdx.x;
    const int wid  = tid >> 5, lane = tid & 31;
    const int g    = lane >> 2, tg = lane & 3;
    const int mw   = wid >> 3, nw = wid & 7;
    const int blk  = blockIdx.x;
    const int bt0  = blk * MROWS;

    if (tid == 0) {
        mbar_init(sb + SM_MBAR, 1);
        fence_async();
        mbar_expect_tx(sb + SM_MBAR, WBYTES);
        bulk_g2s(sb + SM_WHH, g_Whh, WBYTES, sb + SM_MBAR);
    }
    int* sact = (int*)(smem + SM_ACT);
    if (tid < MROWS) sact[tid] = g_active[bt0 + tid];
    __syncthreads();

    const uint32_t lrow = lane & 15;
    const uint32_t lcol = (lane & 16) ? 16u : 0u;
    const uint32_t aoff = (mw*64 + lrow)*ROWB + lcol;

    const int rbase = mw*64 + g + ((tg & 1) ? 8 : 0);

    float creg[4][8];
#pragma unroll
    for (int q = 0; q < 4; q++)
#pragma unroll
        for (int i = 0; i < 8; i++) creg[q][i] = 0.0f;

    const uint4* gxin = g_gx + ((size_t)blk*NTHR + tid)*16;
    const size_t pstride = (size_t)NBLK*NTHR*16;

    uint4 nxt[4];
#pragma unroll
    for (int i = 0; i < 4; i++) nxt[i] = gxin[i];   // (p=0,q=0)

    bool whh_ready = false;

    for (int p = 0; p < PP; p++) {
        const uint32_t rd_b = sb + ((p & 1) ? SM_AH0 : SM_AH1) + aoff;   // h from step p-1
        char* wrbuf = smem + ((p & 1) ? SM_AH1 : SM_AH0);
        if (p == 1 && !whh_ready) { mbar_wait(sb + SM_MBAR, 0); whh_ready = true; }

#pragma unroll
        for (int q = 0; q < 4; q++) {
            // unpack gx (raw fragment layout) into accumulators
            float d[4][2][4];
            uint32_t gq[16];
#pragma unroll
            for (int i = 0; i < 4; i++) {
                gq[4*i]   = nxt[i].x; gq[4*i+1] = nxt[i].y;
                gq[4*i+2] = nxt[i].z; gq[4*i+3] = nxt[i].w;
            }
#pragma unroll
            for (int ni = 0; ni < 2; ni++)
#pragma unroll
                for (int mi = 0; mi < 4; mi++) {
                    float2 v01 = __half22float2(*(__half2*)&gq[(ni*4+mi)*2]);
                    float2 v23 = __half22float2(*(__half2*)&gq[(ni*4+mi)*2 + 1]);
                    d[mi][ni][0] = v01.x; d[mi][ni][1] = v01.y;
                    d[mi][ni][2] = v23.x; d[mi][ni][3] = v23.y;
                }
            // prefetch next (q+1) or (p+1, q=0)
            {
                int s = p*4 + q + 1;
                if (s < PP*4) {
                    const uint4* src = g_gx + ((size_t)(s >> 2))*pstride
                                     + ((size_t)blk*NTHR + tid)*16 + (s & 3)*4;
#pragma unroll
                    for (int i = 0; i < 4; i++) nxt[i] = src[i];
                }
            }

            if (p > 0)
                gemm_pass(rd_b, smem + SM_WHH + q*CHUNK, nw, g, tg, d);

            // epilogue (raw -> gate exchange, same mapping as validated R8)
#pragma unroll
            for (int ni = 0; ni < 2; ni++) {
                const int j = q*32 + nw*4 + ni*2 + (tg >> 1);
#pragma unroll
                for (int mi = 0; mi < 4; mi++) {
                    float d0 = d[mi][ni][0], d1 = d[mi][ni][1];
                    float d2 = d[mi][ni][2], d3 = d[mi][ni][3];
                    float s0 = __shfl_xor_sync(0xffffffffu, d0, 1);
                    float s1 = __shfl_xor_sync(0xffffffffu, d1, 1);
                    float s2 = __shfl_xor_sync(0xffffffffu, d2, 1);
                    float s3 = __shfl_xor_sync(0xffffffffu, d3, 1);
                    float gi, gf, gg, go;
                    if ((tg & 1) == 0) { gi = d0; gf = d1; gg = s0; go = s1; }
                    else               { gi = s2; gf = s3; gg = d2; go = d3; }
                    float& cc = creg[q][mi*2 + ni];
                    cc = sigf(gf) * cc + sigf(gi) * tanhf_(gg);
                    float h = sigf(go) * tanhf_(cc);
                    const int r = rbase + mi*16;
                    if (p < PP - 1) {
                        *(__half*)(wrbuf + r*ROWB + j*2) = __float2half(h);
                    } else {
                        out[(size_t)(bt0 + r)*DD + j] = sact[r] ? h : 0.0f;
                    }
                }
            }
        }
        __syncthreads();   // scatter visible; read buffer free for overwrite
    }
}

// ---------------------------------------------------------------------------
extern "C" void kernel_launch(void* const* d_in, const int* in_sizes, int n_in,
                              void* d_out, int out_size) {
    const float* cross    = (const float*)d_in[0];
    const float* node_emb = (const float*)d_in[1];
    const float* w_ih     = (const float*)d_in[2];
    const float* w_hh     = (const float*)d_in[3];
    const float* b_ih     = (const float*)d_in[4];
    const float* b_hh     = (const float*)d_in[5];
    const int*   paths    = (const int*)d_in[6];
    float* out = (float*)d_out;

    cudaFuncSetAttribute(gx_kernel, cudaFuncAttributeMaxDynamicSharedMemorySize, SMEM_GX);
    cudaFuncSetAttribute(lstm_mma, cudaFuncAttributeMaxDynamicSharedMemorySize, SMEM_SZ);

    prep_kernel<<<(2*NG*DD + 255)/256, 256>>>(w_ih, w_hh, b_ih, b_hh);
    leaf_kernel<<<(NSEQ*32 + 127)/128, 128>>>(cross, paths);
    gx_kernel<<<dim3(NBLK, PP), NTHR, SMEM_GX>>>(node_emb);
    lstm_mma<<<NBLK, NTHR, SMEM_SZ>>>(out);
}

// round 10
// speedup vs baseline: 1.7279x; 1.7279x over previous
#include <cuda_runtime.h>
#include <cuda_fp16.h>
#include <cstdint>

#define BB   512
#define TT   100
#define LL   256
#define DD   128
#define PP   9
#define NSEQ (BB*TT)
#define NG   512
#define MROWS 128
#define NBLK (NSEQ/MROWS)   // 400
#define NTHR 512
#define ROWB  272            // padded row stride bytes
#define CHUNK (128*ROWB)     // 34816
#define PAIRB (2*CHUNK)      // 69632: [Wih_q | Whh_q]

// SMEM layout (dynamic)
#define SM_AX   0            // 34816 x tile
#define SM_AH   34816        // 34816 h tile
#define SM_W    69632        // 2 x PAIRB ring -> ends 208896
#define SM_BIAS 208896       // 2048
#define SM_NID  210944       // 4608
#define SM_ACT  215552       // 512
#define SM_MBAR 216064       // 16
#define SMEM_SZ 216192

__device__ __align__(128) unsigned char g_Bimg[4*PAIRB];
__device__ float g_bias[NG];
__device__ int   g_nids[NSEQ*PP];
__device__ int   g_active[NSEQ];

__device__ __forceinline__ float sigf(float x)   { return 1.0f / (1.0f + __expf(-x)); }
__device__ __forceinline__ float tanhf_(float x) { return 1.0f - 2.0f / (__expf(2.0f*x) + 1.0f); }

__device__ __forceinline__ uint32_t smem_u32(const void* p) {
    uint32_t a;
    asm("{ .reg .u64 t; cvta.to.shared.u64 t, %1; cvt.u32.u64 %0, t; }" : "=r"(a) : "l"(p));
    return a;
}
__device__ __forceinline__ void mbar_init(uint32_t mbar, uint32_t cnt) {
    asm volatile("mbarrier.init.shared.b64 [%0], %1;" :: "r"(mbar), "r"(cnt) : "memory");
}
__device__ __forceinline__ void mbar_expect_tx(uint32_t mbar, uint32_t bytes) {
    asm volatile("mbarrier.arrive.expect_tx.shared.b64 _, [%0], %1;" :: "r"(mbar), "r"(bytes) : "memory");
}
__device__ __forceinline__ void mbar_wait(uint32_t mbar, uint32_t ph) {
    asm volatile(
        "{\n\t.reg .pred P;\n\tLW_%=:\n\t"
        "mbarrier.try_wait.parity.acquire.cta.shared::cta.b64 P, [%0], %1, 0x989680;\n\t"
        "@P bra LD_%=;\n\tbra LW_%=;\n\tLD_%=:\n\t}"
        :: "r"(mbar), "r"(ph) : "memory");
}
__device__ __forceinline__ void bulk_g2s(uint32_t dst, const void* src, uint32_t bytes, uint32_t mbar) {
    asm volatile(
        "cp.async.bulk.shared::cluster.global.mbarrier::complete_tx::bytes [%0], [%1], %2, [%3];"
        :: "r"(dst), "l"(src), "r"(bytes), "r"(mbar) : "memory");
}
__device__ __forceinline__ void mma16816h(float* d, const uint32_t* a, const uint32_t* b) {
    asm volatile(
        "mma.sync.aligned.m16n8k16.row.col.f32.f16.f16.f32 "
        "{%0,%1,%2,%3}, {%4,%5,%6,%7}, {%8,%9}, {%0,%1,%2,%3};"
        : "+f"(d[0]), "+f"(d[1]), "+f"(d[2]), "+f"(d[3])
        : "r"(a[0]), "r"(a[1]), "r"(a[2]), "r"(a[3]), "r"(b[0]), "r"(b[1]));
}
__device__ __forceinline__ void ldsm4(uint32_t* r, uint32_t addr) {
    asm volatile("ldmatrix.sync.aligned.m8n8.x4.shared.b16 {%0,%1,%2,%3}, [%4];"
        : "=r"(r[0]), "=r"(r[1]), "=r"(r[2]), "=r"(r[3]) : "r"(addr));
}

// One [64m x 16n x 128k] warp product-accumulate (fp16 operands).
__device__ __forceinline__ void gemm_pass(uint32_t abase, const char* __restrict__ W,
                                          int nw, int g, int tg, float d[4][2][4]) {
#pragma unroll
    for (int k8 = 0; k8 < 8; k8++) {
        uint32_t a[4][4], b[2][2];
#pragma unroll
        for (int mi = 0; mi < 4; mi++)
            ldsm4(a[mi], abase + mi*(16*ROWB) + k8*32);
        const int kb = (k8*16 + tg*2) * 2;
#pragma unroll
        for (int ni = 0; ni < 2; ni++) {
            const char* wr = W + (nw*16 + ni*8 + g)*ROWB + kb;
            b[ni][0] = *(const uint32_t*)wr;
            b[ni][1] = *(const uint32_t*)(wr + 16);
        }
#pragma unroll
        for (int mi = 0; mi < 4; mi++)
#pragma unroll
            for (int ni = 0; ni < 2; ni++)
                mma16816h(d[mi][ni], a[mi], b[ni]);
    }
}

// ---------------------------------------------------------------------------
// prep: fp16 W image; pair q = [Wih_q | Whh_q], row n=(j&31)*4+gate, 272B rows
// ---------------------------------------------------------------------------
__global__ void prep_kernel(const float* __restrict__ w_ih, const float* __restrict__ w_hh,
                            const float* __restrict__ b_ih, const float* __restrict__ b_hh) {
    int idx = blockIdx.x * blockDim.x + threadIdx.x;
    if (idx < NG) g_bias[idx] = b_ih[idx] + b_hh[idx];
    if (idx >= 2 * NG * DD) return;
    int part = idx >> 16;          // 0: Wih, 1: Whh
    int rem  = idx & 65535;
    int r = rem >> 7;
    int k = rem & 127;
    int gate = r >> 7, j = r & 127;
    int q = j >> 5;
    int n = ((j & 31) << 2) | gate;
    float w = (part == 0) ? w_ih[r * DD + k] : w_hh[r * DD + k];
    *(__half*)((char*)g_Bimg + q*PAIRB + part*CHUNK + n*ROWB + k*2) = __float2half(w);
}

// ---------------------------------------------------------------------------
__global__ void leaf_kernel(const float* __restrict__ cross, const int* __restrict__ paths) {
    int warp = (blockIdx.x * blockDim.x + threadIdx.x) >> 5;
    int lane = threadIdx.x & 31;
    if (warp >= NSEQ) return;
    int b = warp / TT;
    int t = warp - b * TT;
    const float* row = cross + (size_t)b * (TT*LL) + (size_t)t * LL;
    float bv = -3.0e38f; int bl = 0; int anyp = 0;
#pragma unroll
    for (int i = 0; i < LL/32; i++) {
        int l = lane + 32*i;
        float v = row[l];
        if (v > 0.0f) anyp = 1;
        if (v > bv) { bv = v; bl = l; }
    }
#pragma unroll
    for (int off = 16; off > 0; off >>= 1) {
        float ov = __shfl_down_sync(0xffffffffu, bv, off);
        int   ol = __shfl_down_sync(0xffffffffu, bl, off);
        if (ov > bv || (ov == bv && ol < bl)) { bv = ov; bl = ol; }
    }
    anyp = __any_sync(0xffffffffu, anyp);
    int leaf = __shfl_sync(0xffffffffu, bl, 0);
    if (lane < PP) g_nids[warp*PP + lane] = paths[((size_t)t*LL + leaf)*PP + lane];
    if (lane == 0) g_active[warp] = anyp;
}

// ---------------------------------------------------------------------------
__global__ void __launch_bounds__(NTHR, 1)
lstm_mma(const float* __restrict__ node_emb, float* __restrict__ out) {
    extern __shared__ __align__(16) char smem[];
    const uint32_t sb = smem_u32(smem);
    const int tid  = threadIdx.x;
    const int wid  = tid >> 5, lane = tid & 31;
    const int g    = lane >> 2, tg = lane & 3;
    const int mw   = wid >> 3, nw = wid & 7;        // 2 x 8 warp grid
    const int bt0  = blockIdx.x * MROWS;

    int* snid   = (int*)(smem + SM_NID);
    int* sact   = (int*)(smem + SM_ACT);
    float* sbias = (float*)(smem + SM_BIAS);
    for (int i = tid; i < MROWS*PP; i += NTHR) snid[i] = g_nids[bt0*PP + i];
    for (int i = tid; i < MROWS; i += NTHR)    sact[i] = g_active[bt0 + i];
    for (int i = tid; i < NG; i += NTHR)       sbias[i] = g_bias[i];
    if (tid == 0) { mbar_init(sb + SM_MBAR, 1); mbar_init(sb + SM_MBAR + 8, 1); }
    __syncthreads();

    const uint32_t lrow = lane & 15;
    const uint32_t lcol = (lane & 16) ? 16u : 0u;
    const uint32_t aoff = (mw*64 + lrow) * ROWB + lcol;
    const uint32_t ax_b = sb + SM_AX + aoff;
    const uint32_t ah_b = sb + SM_AH + aoff;

    const int rbase = mw*64 + g + ((tg & 1) ? 8 : 0);   // epilogue row base

    float creg[4][8], hkeep[4][8];
#pragma unroll
    for (int q = 0; q < 4; q++)
#pragma unroll
        for (int i = 0; i < 8; i++) creg[q][i] = 0.0f;

    int icnt = 0, ccnt = 0;
    auto issue = [&](int pq) {
        if (tid == 0) {
            uint32_t mb = sb + SM_MBAR + 8*(icnt & 1);
            mbar_expect_tx(mb, PAIRB);
            bulk_g2s(sb + SM_W + (icnt & 1)*PAIRB,
                     (const char*)g_Bimg + (size_t)pq*PAIRB, PAIRB, mb);
        }
        icnt++;
    };

    for (int p = 0; p < PP; p++) {
        // issue first two pair-chunks BEFORE the gather (overlap transfers)
        issue(0); issue(1);

        // ---- gather x_p into A_x (fp16) ----
#pragma unroll
        for (int i = 0; i < 8; i++) {
            int idx = i * NTHR + tid;          // 4096 float4 items
            int mm = idx >> 5, kq = (idx & 31) << 2;
            const float4 v = *(const float4*)(node_emb + (size_t)snid[mm*PP + p]*DD + kq);
            __half2 a = __floats2half2_rn(v.x, v.y);
            __half2 b = __floats2half2_rn(v.z, v.w);
            uint2 pk; pk.x = *(uint32_t*)&a; pk.y = *(uint32_t*)&b;
            *(uint2*)(smem + SM_AX + mm*ROWB + kq*2) = pk;
        }
        __syncthreads();   // x + prev-step h scatter visible to all warps

#pragma unroll
        for (int q = 0; q < 4; q++) {
            mbar_wait(sb + SM_MBAR + 8*(ccnt & 1), (ccnt >> 1) & 1);
            const char* W = smem + SM_W + (ccnt & 1)*PAIRB;
            ccnt++;

            float d[4][2][4];
#pragma unroll
            for (int mi = 0; mi < 4; mi++)
#pragma unroll
                for (int ni = 0; ni < 2; ni++)
#pragma unroll
                    for (int e = 0; e < 4; e++) d[mi][ni][e] = 0.0f;

            gemm_pass(ax_b, W, nw, g, tg, d);               // x @ Wih_q
            if (p > 0)
                gemm_pass(ah_b, W + CHUNK, nw, g, tg, d);   // h @ Whh_q

            __syncthreads();   // all warps done with this W buffer
            if (q + 2 < 4) issue(q + 2);

            // ---- epilogue for quarter q (overlaps next transfers) ----
#pragma unroll
            for (int ni = 0; ni < 2; ni++) {
                const int j = q*32 + nw*4 + ni*2 + (tg >> 1);
                const float bi = sbias[j],       bfv = sbias[128 + j];
                const float bg = sbias[256 + j], bo  = sbias[384 + j];
#pragma unroll
                for (int mi = 0; mi < 4; mi++) {
                    float d0 = d[mi][ni][0], d1 = d[mi][ni][1];
                    float d2 = d[mi][ni][2], d3 = d[mi][ni][3];
                    float s0 = __shfl_xor_sync(0xffffffffu, d0, 1);
                    float s1 = __shfl_xor_sync(0xffffffffu, d1, 1);
                    float s2 = __shfl_xor_sync(0xffffffffu, d2, 1);
                    float s3 = __shfl_xor_sync(0xffffffffu, d3, 1);
                    float gi, gf, gg, go;
                    if ((tg & 1) == 0) { gi = d0; gf = d1; gg = s0; go = s1; }
                    else               { gi = s2; gf = s3; gg = d2; go = d3; }
                    float& cc = creg[q][mi*2 + ni];
                    cc = sigf(gf + bfv) * cc + sigf(gi + bi) * tanhf_(gg + bg);
                    float h = sigf(go + bo) * tanhf_(cc);
                    hkeep[q][mi*2 + ni] = h;
                    if (p == PP - 1) {
                        const int r = rbase + mi*16;
                        out[(size_t)(bt0 + r)*DD + j] = sact[r] ? h : 0.0f;
                    }
                }
            }
        }

        if (p < PP - 1) {
            // scatter all h for next step (old A_h fully consumed this step;
            // made visible to all warps by next iteration's post-gather sync)
#pragma unroll
            for (int q = 0; q < 4; q++)
#pragma unroll
                for (int ni = 0; ni < 2; ni++) {
                    const int j = q*32 + nw*4 + ni*2 + (tg >> 1);
#pragma unroll
                    for (int mi = 0; mi < 4; mi++) {
                        const int r = rbase + mi*16;
                        *(__half*)(smem + SM_AH + r*ROWB + j*2) =
                            __float2half(hkeep[q][mi*2 + ni]);
                    }
                }
        }
    }
}

// ---------------------------------------------------------------------------
extern "C" void kernel_launch(void* const* d_in, const int* in_sizes, int n_in,
                              void* d_out, int out_size) {
    const float* cross    = (const float*)d_in[0];
    const float* node_emb = (const float*)d_in[1];
    const float* w_ih     = (const float*)d_in[2];
    const float* w_hh     = (const float*)d_in[3];
    const float* b_ih     = (const float*)d_in[4];
    const float* b_hh     = (const float*)d_in[5];
    const int*   paths    = (const int*)d_in[6];
    float* out = (float*)d_out;

    cudaFuncSetAttribute(lstm_mma, cudaFuncAttributeMaxDynamicSharedMemorySize, SMEM_SZ);
    prep_kernel<<<(2*NG*DD + 255)/256, 256>>>(w_ih, w_hh, b_ih, b_hh);
    leaf_kernel<<<(NSEQ*32 + 127)/128, 128>>>(cross, paths);
    lstm_mma<<<NBLK, NTHR, SMEM_SZ>>>(node_emb, out);
}